// round 2
// baseline (speedup 1.0000x reference)
#include <cuda_runtime.h>

#define N_NODES 8192
#define N_EDGES 262144
#define NH 8
#define NC 128
#define IN_DIM 128
#define HC 1024
#define TOTAL_E (N_EDGES + N_NODES)

// ---------------- device scratch (no allocations allowed) ----------------
__device__ float g_asrc[2][N_NODES * NH];
__device__ float g_adst[2][N_NODES * NH];
__device__ float g_den [2][N_NODES * NH];
__device__ float g_wsrc[2][N_NODES * NH];
__device__ float g_usrc[2][IN_DIM * NH];
__device__ float g_udst[2][IN_DIM * NH];
__device__ float g_G   [2][NH * IN_DIM];
__device__ float g_memb[2][HC];
__device__ int   g_is64;

// ---------------- zero scratch + detect edge index dtype ----------------
__global__ void k_zero_detect(const int* e1) {
    int t = blockIdx.x * blockDim.x + threadIdx.x;
    if (t < 2 * N_NODES * NH) {
        ((float*)g_den)[t]  = 0.0f;
        ((float*)g_wsrc)[t] = 0.0f;
    }
    if (t < 2 * NH * IN_DIM) ((float*)g_G)[t] = 0.0f;
    if (t == 0) {
        // int64 little-endian with values < 8192 -> every odd 32-bit word is 0.
        // For int32 data the odd words are node ids (P(all 64 zero) ~ 0).
        int all0 = 1;
        #pragma unroll
        for (int i = 0; i < 64; i++)
            if (e1[2 * i + 1] != 0) { all0 = 0; break; }
        g_is64 = all0;
    }
}

// ---------------- fold W and att into u[k][h] = sum_c W[k, h*C+c]*att[h,c] ----------------
__global__ void k_u(const float* __restrict__ W,
                    const float* __restrict__ att_src,
                    const float* __restrict__ att_dst, int g) {
    int t = blockIdx.x * blockDim.x + threadIdx.x;
    if (t >= 2 * IN_DIM * NH) return;
    int which = t / (IN_DIM * NH);
    int r = t - which * (IN_DIM * NH);
    int k = r / NH, hh = r - (r / NH) * NH;
    const float* att = which ? att_dst : att_src;
    const float* wrow = W + k * HC + hh * NC;
    const float* arow = att + hh * NC;
    float s = 0.0f;
    #pragma unroll 8
    for (int c = 0; c < NC; c++) s += wrow[c] * arow[c];
    if (which) g_udst[g][k * NH + hh] = s;
    else       g_usrc[g][k * NH + hh] = s;
}

// ---------------- a_src/a_dst = x @ u  ([8192,8] each) ----------------
__global__ void k_a(const float* __restrict__ x, int g) {
    int t = blockIdx.x * blockDim.x + threadIdx.x;
    if (t >= N_NODES * NH) return;
    int n = t >> 3, hh = t & 7;
    const float* xr = x + n * IN_DIM;
    const float* us = g_usrc[g];
    const float* ud = g_udst[g];
    float as = 0.0f, ad = 0.0f;
    #pragma unroll 4
    for (int k = 0; k < IN_DIM; k++) {
        float xv = xr[k];
        as += xv * us[k * NH + hh];
        ad += xv * ud[k * NH + hh];
    }
    g_asrc[g][t] = as;
    g_adst[g][t] = ad;
}

// ---------------- edge helpers ----------------
__device__ __forceinline__ void get_edge(const int* __restrict__ e32, int idx,
                                         int is64, int& src, int& dst) {
    if (is64) { src = e32[2 * idx];  dst = e32[2 * (N_EDGES + idx)]; }
    else      { src = e32[idx];      dst = e32[N_EDGES + idx]; }
}

__device__ __forceinline__ void edge_exp(int g, int src, int dst, float* ex) {
    const float4* as4 = reinterpret_cast<const float4*>(g_asrc[g] + src * NH);
    const float4* ad4 = reinterpret_cast<const float4*>(g_adst[g] + dst * NH);
    float4 s0 = as4[0], s1 = as4[1], d0 = ad4[0], d1 = ad4[1];
    float ev[8] = { s0.x + d0.x, s0.y + d0.y, s0.z + d0.z, s0.w + d0.w,
                    s1.x + d1.x, s1.y + d1.y, s1.z + d1.z, s1.w + d1.w };
    #pragma unroll
    for (int h = 0; h < 8; h++) {
        float v = ev[h];
        v = (v > 0.0f) ? v : 0.2f * v;   // leaky_relu, slope 0.2
        ex[h] = __expf(v);
    }
}

// ---------------- pass 1: den[dst,h] += exp(e) ----------------
__global__ void k_den(const int* __restrict__ e32, int g) {
    int idx = blockIdx.x * blockDim.x + threadIdx.x;
    if (idx >= TOTAL_E) return;
    int is64 = g_is64;
    int src, dst;
    if (idx < N_EDGES) get_edge(e32, idx, is64, src, dst);
    else { src = dst = idx - N_EDGES; }   // self loops
    float ex[8];
    edge_exp(g, src, dst, ex);
    float* den = g_den[g] + dst * NH;
    #pragma unroll
    for (int h = 0; h < 8; h++) atomicAdd(den + h, ex[h]);
}

// ---------------- pass 2: Wsrc[src,h] += exp(e)/den[dst,h] ----------------
__global__ void k_wsrc(const int* __restrict__ e32, int g) {
    int idx = blockIdx.x * blockDim.x + threadIdx.x;
    if (idx >= TOTAL_E) return;
    int is64 = g_is64;
    int src, dst;
    if (idx < N_EDGES) get_edge(e32, idx, is64, src, dst);
    else { src = dst = idx - N_EDGES; }
    float ex[8];
    edge_exp(g, src, dst, ex);
    const float4* dn4 = reinterpret_cast<const float4*>(g_den[g] + dst * NH);
    float4 n0 = dn4[0], n1 = dn4[1];
    float dn[8] = { n0.x, n0.y, n0.z, n0.w, n1.x, n1.y, n1.z, n1.w };
    float* ws = g_wsrc[g] + src * NH;
    #pragma unroll
    for (int h = 0; h < 8; h++) atomicAdd(ws + h, __fdividef(ex[h], dn[h]));
}

// ---------------- G[h,k] = sum_n Wsrc[n,h] * x[n,k]  ([8,128]) ----------------
__global__ void k_G(const float* __restrict__ x, int g) {
    int k  = threadIdx.x;            // 128 threads
    int n0 = blockIdx.x * 128;       // 64 blocks x 128 nodes
    float acc[NH];
    #pragma unroll
    for (int h = 0; h < NH; h++) acc[h] = 0.0f;
    for (int i = 0; i < 128; i++) {
        int n = n0 + i;
        float xv = x[n * IN_DIM + k];
        const float* w = g_wsrc[g] + n * NH;
        #pragma unroll
        for (int h = 0; h < NH; h++) acc[h] += w[h] * xv;
    }
    #pragma unroll
    for (int h = 0; h < NH; h++) atomicAdd(&g_G[g][h * IN_DIM + k], acc[h]);
}

// ---------------- mean_emb[j] = (sum_k G[h,k] * W[k,j]) / N + b[j] ----------------
__global__ void k_emb(const float* __restrict__ W, const float* __restrict__ b, int g) {
    int j = blockIdx.x * blockDim.x + threadIdx.x;  // 1024
    if (j >= HC) return;
    int hh = j >> 7;
    const float* Gr = g_G[g] + hh * IN_DIM;
    float s = 0.0f;
    #pragma unroll 4
    for (int k = 0; k < IN_DIM; k++) s += Gr[k] * W[k * HC + j];
    g_memb[g][j] = s * (1.0f / N_NODES) + b[j];
}

// ---------------- out[0:128] = memb(graph2)@Wl+bl ; out[128:256] = memb(graph1)@Wl+bl ----
__global__ void k_out(const float* __restrict__ Wl, const float* __restrict__ bl,
                      float* __restrict__ out) {
    int c = threadIdx.x;     // 128
    int blk = blockIdx.x;    // 0 -> graph 2 result, 1 -> graph 1 result
    const float* m = g_memb[blk == 0 ? 1 : 0];
    float s = 0.0f;
    #pragma unroll 4
    for (int j = 0; j < HC; j++) s += m[j] * Wl[j * 128 + c];
    out[blk * 128 + c] = s + bl[c];
}

extern "C" void kernel_launch(void* const* d_in, const int* in_sizes, int n_in,
                              void* d_out, int out_size) {
    const float* x1  = (const float*)d_in[0];
    const int*   e1  = (const int*)  d_in[1];
    const float* W1  = (const float*)d_in[2];
    const float* as1 = (const float*)d_in[3];
    const float* ad1 = (const float*)d_in[4];
    const float* b1  = (const float*)d_in[5];
    const float* x2  = (const float*)d_in[6];
    const int*   e2  = (const int*)  d_in[7];
    const float* W2  = (const float*)d_in[8];
    const float* as2 = (const float*)d_in[9];
    const float* ad2 = (const float*)d_in[10];
    const float* b2  = (const float*)d_in[11];
    const float* Wl  = (const float*)d_in[12];
    const float* bl  = (const float*)d_in[13];
    float* out = (float*)d_out;

    k_zero_detect<<<(2 * N_NODES * NH + 255) / 256, 256>>>(e1);

    const float* xs[2]   = {x1, x2};
    const int*   es[2]   = {e1, e2};
    const float* Ws[2]   = {W1, W2};
    const float* atts[2] = {as1, as2};
    const float* attd[2] = {ad1, ad2};
    const float* bs[2]   = {b1, b2};

    for (int g = 0; g < 2; g++) {
        k_u   <<<8, 256>>>(Ws[g], atts[g], attd[g], g);
        k_a   <<<(N_NODES * NH + 255) / 256, 256>>>(xs[g], g);
        k_den <<<(TOTAL_E + 255) / 256, 256>>>(es[g], g);
        k_wsrc<<<(TOTAL_E + 255) / 256, 256>>>(es[g], g);
        k_G   <<<N_NODES / 128, 128>>>(xs[g], g);
        k_emb <<<4, 256>>>(Ws[g], bs[g], g);
    }
    k_out<<<2, 128>>>(Wl, bl, out);
}

// round 3
// speedup vs baseline: 1.7934x; 1.7934x over previous
#include <cuda_runtime.h>

#define N_NODES 8192
#define N_EDGES 262144
#define NH 8
#define NC 128
#define IN_DIM 128
#define HC 1024
#define TOTAL_E (N_EDGES + N_NODES)
#define NA (N_NODES * NH)

// ---------------- device scratch (no allocations allowed) ----------------
__device__ __align__(128) float g_asrc[2][NA];
__device__ __align__(128) float g_adst[2][NA];
__device__ __align__(128) float g_den [2][NA];
__device__ __align__(128) float g_rden[2][NA];
__device__ __align__(128) float g_wsrc[2][NA];
__device__ __align__(128) float g_ex  [2][TOTAL_E * NH];   // per-edge exp, 17.3MB
__device__ __align__(128) float g_usrc[2][IN_DIM * NH];
__device__ __align__(128) float g_udst[2][IN_DIM * NH];
__device__ __align__(128) float g_G   [2][NH * IN_DIM];
__device__ __align__(128) float g_memb[2][HC];
__device__ int g_is64;

__device__ __forceinline__ void red_add_v4(float* p, float a, float b, float c, float d) {
    asm volatile("red.global.add.v4.f32 [%0], {%1,%2,%3,%4};"
                 :: "l"(p), "f"(a), "f"(b), "f"(c), "f"(d) : "memory");
}

// ---------------- zero scratch + detect edge index dtype ----------------
__global__ void k_zero_detect(const int* e1) {
    int t = blockIdx.x * blockDim.x + threadIdx.x;
    if (t < 2 * NA) {
        ((float*)g_den)[t]  = 0.0f;
        ((float*)g_wsrc)[t] = 0.0f;
    }
    if (t < 2 * NH * IN_DIM) ((float*)g_G)[t] = 0.0f;
    if (t == 0) {
        // int64 little-endian with values < 8192 -> every odd 32-bit word is 0.
        int all0 = 1;
        #pragma unroll
        for (int i = 0; i < 64; i++)
            if (e1[2 * i + 1] != 0) { all0 = 0; break; }
        g_is64 = all0;
    }
}

// ---------------- fold W and att: u[k][h] = sum_c W[k, h*C+c]*att[h,c] ----------------
__global__ void k_u(const float* __restrict__ W1, const float* __restrict__ as1,
                    const float* __restrict__ ad1,
                    const float* __restrict__ W2, const float* __restrict__ as2,
                    const float* __restrict__ ad2) {
    int t = blockIdx.x * blockDim.x + threadIdx.x;     // 2 graphs * 2 kinds * 1024
    if (t >= 4 * IN_DIM * NH) return;
    int g = t >> 11;
    int r = t & 2047;
    int which = r >> 10;                               // 0=src 1=dst
    int q = r & 1023;
    int k = q >> 3, hh = q & 7;
    const float* W   = g ? W2 : W1;
    const float* att = g ? (which ? ad2 : as2) : (which ? ad1 : as1);
    const float* wrow = W + k * HC + hh * NC;
    const float* arow = att + hh * NC;
    float s = 0.0f;
    #pragma unroll 8
    for (int c = 0; c < NC; c++) s += wrow[c] * arow[c];
    if (which) g_udst[g][k * NH + hh] = s;
    else       g_usrc[g][k * NH + hh] = s;
}

// ---------------- a_src/a_dst = x @ u ----------------
__global__ void k_a(const float* __restrict__ x1, const float* __restrict__ x2) {
    int t = blockIdx.x * blockDim.x + threadIdx.x;     // 2 * 65536
    if (t >= 2 * NA) return;
    int g = t >> 16;
    int r = t & (NA - 1);
    int n = r >> 3, hh = r & 7;
    const float* x  = g ? x2 : x1;
    const float* xr = x + n * IN_DIM;
    const float* us = g_usrc[g];
    const float* ud = g_udst[g];
    float as = 0.0f, ad = 0.0f;
    #pragma unroll 4
    for (int k = 0; k < IN_DIM; k++) {
        float xv = xr[k];
        as += xv * us[k * NH + hh];
        ad += xv * ud[k * NH + hh];
    }
    g_asrc[g][r] = as;
    g_adst[g][r] = ad;
}

// ---------------- pass 1: ex = exp(lrelu(a_src[src]+a_dst[dst])); den[dst] += ex ------
__global__ void k_den(const int* __restrict__ e1, const int* __restrict__ e2) {
    int t = blockIdx.x * blockDim.x + threadIdx.x;
    if (t >= 2 * TOTAL_E) return;
    int g = (t >= TOTAL_E);
    int idx = t - g * TOTAL_E;
    const int* e32 = g ? e2 : e1;
    int is64 = g_is64;
    int src, dst;
    if (idx < N_EDGES) {
        if (is64) { src = e32[2 * idx]; dst = e32[2 * (N_EDGES + idx)]; }
        else      { src = e32[idx];     dst = e32[N_EDGES + idx]; }
    } else { src = dst = idx - N_EDGES; }

    const float4* as4 = reinterpret_cast<const float4*>(g_asrc[g] + src * NH);
    const float4* ad4 = reinterpret_cast<const float4*>(g_adst[g] + dst * NH);
    float4 s0 = as4[0], s1 = as4[1], d0 = ad4[0], d1 = ad4[1];
    float ev[8] = { s0.x + d0.x, s0.y + d0.y, s0.z + d0.z, s0.w + d0.w,
                    s1.x + d1.x, s1.y + d1.y, s1.z + d1.z, s1.w + d1.w };
    float ex[8];
    #pragma unroll
    for (int h = 0; h < 8; h++) {
        float v = ev[h];
        v = (v > 0.0f) ? v : 0.2f * v;
        ex[h] = __expf(v);
    }
    float4* exo = reinterpret_cast<float4*>(g_ex[g] + (size_t)idx * NH);
    exo[0] = make_float4(ex[0], ex[1], ex[2], ex[3]);
    exo[1] = make_float4(ex[4], ex[5], ex[6], ex[7]);
    float* den = g_den[g] + dst * NH;
    red_add_v4(den,     ex[0], ex[1], ex[2], ex[3]);
    red_add_v4(den + 4, ex[4], ex[5], ex[6], ex[7]);
}

// ---------------- reciprocal of den ----------------
__global__ void k_rcp() {
    int t = blockIdx.x * blockDim.x + threadIdx.x;
    if (t >= 2 * NA) return;
    ((float*)g_rden)[t] = 1.0f / ((float*)g_den)[t];
}

// ---------------- pass 2: Wsrc[src] += ex * rden[dst] ----------------
__global__ void k_wsrc(const int* __restrict__ e1, const int* __restrict__ e2) {
    int t = blockIdx.x * blockDim.x + threadIdx.x;
    if (t >= 2 * TOTAL_E) return;
    int g = (t >= TOTAL_E);
    int idx = t - g * TOTAL_E;
    const int* e32 = g ? e2 : e1;
    int is64 = g_is64;
    int src, dst;
    if (idx < N_EDGES) {
        if (is64) { src = e32[2 * idx]; dst = e32[2 * (N_EDGES + idx)]; }
        else      { src = e32[idx];     dst = e32[N_EDGES + idx]; }
    } else { src = dst = idx - N_EDGES; }

    const float4* exi = reinterpret_cast<const float4*>(g_ex[g] + (size_t)idx * NH);
    float4 x0 = exi[0], x1 = exi[1];
    const float4* rd4 = reinterpret_cast<const float4*>(g_rden[g] + dst * NH);
    float4 r0 = rd4[0], r1 = rd4[1];
    float* ws = g_wsrc[g] + src * NH;
    red_add_v4(ws,     x0.x * r0.x, x0.y * r0.y, x0.z * r0.z, x0.w * r0.w);
    red_add_v4(ws + 4, x1.x * r1.x, x1.y * r1.y, x1.z * r1.z, x1.w * r1.w);
}

// ---------------- G[h,k] = sum_n Wsrc[n,h] * x[n,k] ----------------
__global__ void k_G(const float* __restrict__ x1, const float* __restrict__ x2) {
    int g  = blockIdx.y;
    int k  = threadIdx.x;            // 128 threads
    int n0 = blockIdx.x * 128;       // 64 blocks x 128 nodes
    const float* x = g ? x2 : x1;
    float acc[NH];
    #pragma unroll
    for (int h = 0; h < NH; h++) acc[h] = 0.0f;
    for (int i = 0; i < 128; i++) {
        int n = n0 + i;
        float xv = x[n * IN_DIM + k];
        const float* w = g_wsrc[g] + n * NH;
        #pragma unroll
        for (int h = 0; h < NH; h++) acc[h] += w[h] * xv;
    }
    #pragma unroll
    for (int h = 0; h < NH; h++) atomicAdd(&g_G[g][h * IN_DIM + k], acc[h]);
}

// ---------------- mean_emb[j] = (sum_k G[h,k] * W[k,j]) / N + b[j] ----------------
__global__ void k_emb(const float* __restrict__ W1, const float* __restrict__ b1,
                      const float* __restrict__ W2, const float* __restrict__ b2) {
    int g = blockIdx.y;
    int j = blockIdx.x * blockDim.x + threadIdx.x;  // 1024
    if (j >= HC) return;
    const float* W = g ? W2 : W1;
    const float* b = g ? b2 : b1;
    int hh = j >> 7;
    const float* Gr = g_G[g] + hh * IN_DIM;
    float s = 0.0f;
    #pragma unroll 4
    for (int k = 0; k < IN_DIM; k++) s += Gr[k] * W[k * HC + j];
    g_memb[g][j] = s * (1.0f / N_NODES) + b[j];
}

// ---------------- out[0:128]=memb(g2)@Wl+bl ; out[128:256]=memb(g1)@Wl+bl ----------
__global__ void k_out(const float* __restrict__ Wl, const float* __restrict__ bl,
                      float* __restrict__ out) {
    int c = threadIdx.x;     // 128
    int blk = blockIdx.x;    // 0 -> graph 2 mean, 1 -> graph 1 mean
    const float* m = g_memb[blk == 0 ? 1 : 0];
    float s = 0.0f;
    #pragma unroll 4
    for (int j = 0; j < HC; j++) s += m[j] * Wl[j * 128 + c];
    out[blk * 128 + c] = s + bl[c];
}

extern "C" void kernel_launch(void* const* d_in, const int* in_sizes, int n_in,
                              void* d_out, int out_size) {
    const float* x1  = (const float*)d_in[0];
    const int*   e1  = (const int*)  d_in[1];
    const float* W1  = (const float*)d_in[2];
    const float* as1 = (const float*)d_in[3];
    const float* ad1 = (const float*)d_in[4];
    const float* b1  = (const float*)d_in[5];
    const float* x2  = (const float*)d_in[6];
    const int*   e2  = (const int*)  d_in[7];
    const float* W2  = (const float*)d_in[8];
    const float* as2 = (const float*)d_in[9];
    const float* ad2 = (const float*)d_in[10];
    const float* b2  = (const float*)d_in[11];
    const float* Wl  = (const float*)d_in[12];
    const float* bl  = (const float*)d_in[13];
    float* out = (float*)d_out;

    k_zero_detect<<<(2 * NA + 255) / 256, 256>>>(e1);
    k_u   <<<(4 * IN_DIM * NH + 255) / 256, 256>>>(W1, as1, ad1, W2, as2, ad2);
    k_a   <<<(2 * NA + 255) / 256, 256>>>(x1, x2);
    k_den <<<(2 * TOTAL_E + 255) / 256, 256>>>(e1, e2);
    k_rcp <<<(2 * NA + 255) / 256, 256>>>();
    k_wsrc<<<(2 * TOTAL_E + 255) / 256, 256>>>(e1, e2);
    {
        dim3 grid(N_NODES / 128, 2);
        k_G<<<grid, 128>>>(x1, x2);
    }
    {
        dim3 grid(4, 2);
        k_emb<<<grid, 256>>>(W1, b1, W2, b2);
    }
    k_out<<<2, 128>>>(Wl, bl, out);
}

// round 4
// speedup vs baseline: 2.7016x; 1.5064x over previous
#include <cuda_runtime.h>
#include <cuda_fp16.h>

#define N_NODES 8192
#define N_EDGES 262144
#define NH 8
#define IN_DIM 128
#define HC 1024
#define TOTAL_E (N_EDGES + N_NODES)
#define NA (N_NODES * NH)

// ---------------- device scratch ----------------
__device__ __align__(128) float  g_asrc[2][NA];
__device__ __align__(128) float  g_adst[2][NA];
__device__ __align__(128) float  g_den [2][NA];
__device__ __align__(128) float  g_wsrc[2][NA];
__device__ __align__(128) __half g_ex  [2][TOTAL_E * NH];   // per-edge exp, fp16
__device__ __align__(128) int2   g_edge[2][TOTAL_E];        // decoded (src,dst)
__device__ __align__(128) float  g_usrc[2][IN_DIM * NH];
__device__ __align__(128) float  g_udst[2][IN_DIM * NH];
__device__ __align__(128) float  g_G   [2][NH * IN_DIM];
__device__ int g_is64;

__device__ __forceinline__ void red_add_v4(float* p, float a, float b, float c, float d) {
    asm volatile("red.global.add.v4.f32 [%0], {%1,%2,%3,%4};"
                 :: "l"(p), "f"(a), "f"(b), "f"(c), "f"(d) : "memory");
}

// ======== k_init: zero scratch + dtype detect + fold u = W x att (warp per row) ========
__global__ void k_init(const int* __restrict__ e1,
                       const float* __restrict__ W1, const float* __restrict__ as1,
                       const float* __restrict__ ad1,
                       const float* __restrict__ W2, const float* __restrict__ as2,
                       const float* __restrict__ ad2) {
    int t = blockIdx.x * blockDim.x + threadIdx.x;   // 65536 threads
    // zero den/wsrc (2*NA = 131072 each... actually den & wsrc: 2 arrays of 2*NA/... )
    for (int i = t; i < 2 * NA; i += 65536) {
        ((float*)g_den)[i]  = 0.0f;
        ((float*)g_wsrc)[i] = 0.0f;
    }
    if (t < 2 * NH * IN_DIM) ((float*)g_G)[t] = 0.0f;
    if (t == 0) {
        int all0 = 1;
        #pragma unroll
        for (int i = 0; i < 64; i++)
            if (e1[2 * i + 1] != 0) { all0 = 0; break; }
        g_is64 = all0;
    }
    // u fold: 512 warp tasks (2 graphs x 2 kinds x 128 k-rows)
    int w = t >> 5, lane = t & 31;
    if (w < 512) {
        int g = w >> 8, which = (w >> 7) & 1, k = w & 127;
        const float* W   = g ? W2 : W1;
        const float* att = g ? (which ? ad2 : as2) : (which ? ad1 : as1);
        #pragma unroll
        for (int h = 0; h < 8; h++) {
            float4 wv = *reinterpret_cast<const float4*>(W + k * HC + h * 128 + lane * 4);
            float4 av = *reinterpret_cast<const float4*>(att + h * 128 + lane * 4);
            float s = wv.x * av.x + wv.y * av.y + wv.z * av.z + wv.w * av.w;
            #pragma unroll
            for (int off = 16; off; off >>= 1) s += __shfl_xor_sync(0xffffffffu, s, off);
            if (lane == 0) {
                if (which) g_udst[g][k * NH + h] = s;
                else       g_usrc[g][k * NH + h] = s;
            }
        }
    }
}

// ======== k_a: a = x @ [usrc | udst]  (node per lane, u in shared) ========
__global__ void k_a(const float* __restrict__ x1, const float* __restrict__ x2) {
    __shared__ float su[IN_DIM * 16];          // [k][16]: 0..7 = src, 8..15 = dst
    int g   = blockIdx.y;
    int tid = threadIdx.x;                     // 128
    const float* x = g ? x2 : x1;
    #pragma unroll
    for (int j = 0; j < 8; j++) {
        su[tid * 16 + j]     = g_usrc[g][tid * 8 + j];
        su[tid * 16 + 8 + j] = g_udst[g][tid * 8 + j];
    }
    __syncthreads();

    int n = blockIdx.x * 128 + tid;
    const float4* xr  = reinterpret_cast<const float4*>(x + n * IN_DIM);
    const float4* su4 = reinterpret_cast<const float4*>(su);
    float acc[16];
    #pragma unroll
    for (int j = 0; j < 16; j++) acc[j] = 0.0f;

    #pragma unroll 4
    for (int k4 = 0; k4 < 32; k4++) {
        float4 xv = xr[k4];
        float xs[4] = {xv.x, xv.y, xv.z, xv.w};
        #pragma unroll
        for (int s = 0; s < 4; s++) {
            int b4 = (k4 * 4 + s) * 4;
            float4 u0 = su4[b4], u1 = su4[b4 + 1], u2 = su4[b4 + 2], u3 = su4[b4 + 3];
            acc[0]  += xs[s] * u0.x;  acc[1]  += xs[s] * u0.y;
            acc[2]  += xs[s] * u0.z;  acc[3]  += xs[s] * u0.w;
            acc[4]  += xs[s] * u1.x;  acc[5]  += xs[s] * u1.y;
            acc[6]  += xs[s] * u1.z;  acc[7]  += xs[s] * u1.w;
            acc[8]  += xs[s] * u2.x;  acc[9]  += xs[s] * u2.y;
            acc[10] += xs[s] * u2.z;  acc[11] += xs[s] * u2.w;
            acc[12] += xs[s] * u3.x;  acc[13] += xs[s] * u3.y;
            acc[14] += xs[s] * u3.z;  acc[15] += xs[s] * u3.w;
        }
    }
    float4* oa = reinterpret_cast<float4*>(g_asrc[g] + n * NH);
    float4* od = reinterpret_cast<float4*>(g_adst[g] + n * NH);
    oa[0] = make_float4(acc[0], acc[1], acc[2], acc[3]);
    oa[1] = make_float4(acc[4], acc[5], acc[6], acc[7]);
    od[0] = make_float4(acc[8], acc[9], acc[10], acc[11]);
    od[1] = make_float4(acc[12], acc[13], acc[14], acc[15]);
}

// ======== pass 1: decode edges, ex = exp(lrelu(.)), den[dst] += ex ========
__global__ void k_den(const int* __restrict__ e1, const int* __restrict__ e2) {
    int t = blockIdx.x * blockDim.x + threadIdx.x;
    if (t >= 2 * TOTAL_E) return;
    int g = (t >= TOTAL_E);
    int idx = t - g * TOTAL_E;
    const int* e32 = g ? e2 : e1;
    int src, dst;
    if (idx < N_EDGES) {
        if (g_is64) { src = e32[2 * idx]; dst = e32[2 * (N_EDGES + idx)]; }
        else        { src = e32[idx];     dst = e32[N_EDGES + idx]; }
    } else { src = dst = idx - N_EDGES; }
    g_edge[g][idx] = make_int2(src, dst);

    const float4* as4 = reinterpret_cast<const float4*>(g_asrc[g] + src * NH);
    const float4* ad4 = reinterpret_cast<const float4*>(g_adst[g] + dst * NH);
    float4 s0 = as4[0], s1 = as4[1], d0 = ad4[0], d1 = ad4[1];
    float ev[8] = { s0.x + d0.x, s0.y + d0.y, s0.z + d0.z, s0.w + d0.w,
                    s1.x + d1.x, s1.y + d1.y, s1.z + d1.z, s1.w + d1.w };
    float ex[8];
    #pragma unroll
    for (int h = 0; h < 8; h++) {
        float v = ev[h];
        v = (v > 0.0f) ? v : 0.2f * v;
        ex[h] = __expf(v);
    }
    // fp16 store (16B)
    __half2 hx[4];
    #pragma unroll
    for (int p = 0; p < 4; p++) hx[p] = __floats2half2_rn(ex[2 * p], ex[2 * p + 1]);
    *reinterpret_cast<uint4*>(&g_ex[g][(size_t)idx * NH]) = *reinterpret_cast<uint4*>(hx);

    float* den = g_den[g] + dst * NH;
    red_add_v4(den,     ex[0], ex[1], ex[2], ex[3]);
    red_add_v4(den + 4, ex[4], ex[5], ex[6], ex[7]);
}

// ======== pass 2: Wsrc[src] += ex / den[dst] ========
__global__ void k_wsrc(int dummy) {
    int t = blockIdx.x * blockDim.x + threadIdx.x;
    if (t >= 2 * TOTAL_E) return;
    int g = (t >= TOTAL_E);
    int idx = t - g * TOTAL_E;
    int2 e = g_edge[g][idx];

    uint4 raw = *reinterpret_cast<const uint4*>(&g_ex[g][(size_t)idx * NH]);
    const __half2* hx = reinterpret_cast<const __half2*>(&raw);
    float ex[8];
    #pragma unroll
    for (int p = 0; p < 4; p++) {
        float2 f = __half22float2(hx[p]);
        ex[2 * p] = f.x; ex[2 * p + 1] = f.y;
    }
    const float4* dn4 = reinterpret_cast<const float4*>(g_den[g] + e.y * NH);
    float4 n0 = dn4[0], n1 = dn4[1];
    float dn[8] = { n0.x, n0.y, n0.z, n0.w, n1.x, n1.y, n1.z, n1.w };
    float a[8];
    #pragma unroll
    for (int h = 0; h < 8; h++) a[h] = __fdividef(ex[h], dn[h]);
    float* ws = g_wsrc[g] + e.x * NH;
    red_add_v4(ws,     a[0], a[1], a[2], a[3]);
    red_add_v4(ws + 4, a[4], a[5], a[6], a[7]);
}

// ======== G[h,k] = sum_n Wsrc[n,h] * x[n,k] ========
__global__ void k_G(const float* __restrict__ x1, const float* __restrict__ x2) {
    int g  = blockIdx.y;
    int k  = threadIdx.x;            // 128
    int n0 = blockIdx.x * 128;
    const float* x = g ? x2 : x1;
    float acc[NH];
    #pragma unroll
    for (int h = 0; h < NH; h++) acc[h] = 0.0f;
    for (int i = 0; i < 128; i++) {
        int n = n0 + i;
        float xv = x[n * IN_DIM + k];
        const float4* w4 = reinterpret_cast<const float4*>(g_wsrc[g] + n * NH);
        float4 wa = w4[0], wb = w4[1];
        acc[0] += wa.x * xv; acc[1] += wa.y * xv; acc[2] += wa.z * xv; acc[3] += wa.w * xv;
        acc[4] += wb.x * xv; acc[5] += wb.y * xv; acc[6] += wb.z * xv; acc[7] += wb.w * xv;
    }
    #pragma unroll
    for (int h = 0; h < NH; h++) atomicAdd(&g_G[g][h * IN_DIM + k], acc[h]);
}

// ======== fused tail: memb (shared) then out slice. block b uses graph 1-b ========
__global__ void k_embout(const float* __restrict__ W1, const float* __restrict__ b1,
                         const float* __restrict__ W2, const float* __restrict__ b2,
                         const float* __restrict__ Wl, const float* __restrict__ bl,
                         float* __restrict__ out) {
    __shared__ float sG[HC];       // G for this graph (8*128)
    __shared__ float smemb[HC];
    __shared__ float sred[256];
    int b   = blockIdx.x;          // out slice
    int g   = 1 - b;               // graph whose memb feeds this slice
    int tid = threadIdx.x;         // 256
    const float* W  = g ? W2 : W1;
    const float* bb = g ? b2 : b1;

    #pragma unroll
    for (int i = 0; i < 4; i++) sG[tid + i * 256] = g_G[g][tid + i * 256];
    __syncthreads();

    // stage 1: memb[j] for j = tid*4 .. tid*4+3 (float4 W loads, coalesced)
    {
        int j0 = tid * 4;
        int hh = j0 >> 7;
        const float* Gr = sG + hh * IN_DIM;
        float4 s = make_float4(0.f, 0.f, 0.f, 0.f);
        #pragma unroll 4
        for (int k = 0; k < IN_DIM; k++) {
            float gv = Gr[k];
            float4 w4 = *reinterpret_cast<const float4*>(W + k * HC + j0);
            s.x += gv * w4.x; s.y += gv * w4.y; s.z += gv * w4.z; s.w += gv * w4.w;
        }
        const float inv = 1.0f / N_NODES;
        smemb[j0]     = s.x * inv + bb[j0];
        smemb[j0 + 1] = s.y * inv + bb[j0 + 1];
        smemb[j0 + 2] = s.z * inv + bb[j0 + 2];
        smemb[j0 + 3] = s.w * inv + bb[j0 + 3];
    }
    __syncthreads();

    // stage 2: out[b*128+c] = sum_j smemb[j]*Wl[j*128+c] + bl[c], 2 slices per c
    {
        int c = tid & 127, half = tid >> 7;
        float s = 0.0f;
        #pragma unroll 4
        for (int j = half * 512; j < half * 512 + 512; j++)
            s += smemb[j] * Wl[j * 128 + c];
        sred[tid] = s;
        __syncthreads();
        if (tid < 128)
            out[b * 128 + c] = sred[c] + sred[128 + c] + bl[c];
    }
}

extern "C" void kernel_launch(void* const* d_in, const int* in_sizes, int n_in,
                              void* d_out, int out_size) {
    const float* x1  = (const float*)d_in[0];
    const int*   e1  = (const int*)  d_in[1];
    const float* W1  = (const float*)d_in[2];
    const float* as1 = (const float*)d_in[3];
    const float* ad1 = (const float*)d_in[4];
    const float* b1  = (const float*)d_in[5];
    const float* x2  = (const float*)d_in[6];
    const int*   e2  = (const int*)  d_in[7];
    const float* W2  = (const float*)d_in[8];
    const float* as2 = (const float*)d_in[9];
    const float* ad2 = (const float*)d_in[10];
    const float* b2  = (const float*)d_in[11];
    const float* Wl  = (const float*)d_in[12];
    const float* bl  = (const float*)d_in[13];
    float* out = (float*)d_out;

    k_init<<<256, 256>>>(e1, W1, as1, ad1, W2, as2, ad2);
    {
        dim3 grid(N_NODES / 128, 2);
        k_a<<<grid, 128>>>(x1, x2);
    }
    k_den <<<(2 * TOTAL_E + 255) / 256, 256>>>(e1, e2);
    k_wsrc<<<(2 * TOTAL_E + 255) / 256, 256>>>(0);
    {
        dim3 grid(N_NODES / 128, 2);
        k_G<<<grid, 128>>>(x1, x2);
    }
    k_embout<<<2, 256>>>(W1, b1, W2, b2, Wl, bl, out);
}

// round 5
// speedup vs baseline: 3.1048x; 1.1493x over previous
#include <cuda_runtime.h>
#include <cuda_fp16.h>

#define N_NODES 8192
#define N_EDGES 262144
#define NH 8
#define IN_DIM 128
#define HC 1024
#define TOTAL_E (N_EDGES + N_NODES)
#define NA (N_NODES * NH)

#define NBLK 592
#define NTHR 256
#define TOTNT (NBLK * NTHR)
#define EPT 4                       // edges per thread (4*151552 >= 2*TOTAL_E)

// ---------------- device scratch ----------------
__device__ __align__(128) float g_asrc[2][NA];
__device__ __align__(128) float g_adst[2][NA];
__device__ __align__(128) float g_den [2][NA];
__device__ __align__(128) float g_wsrc[2][NA];
__device__ __align__(128) float g_usrc[2][IN_DIM * NH];
__device__ __align__(128) float g_udst[2][IN_DIM * NH];
__device__ __align__(128) float g_G   [2][NH * IN_DIM];
__device__ int g_is64;

// grid barrier state (count always returns to 0; gen is monotonic across replays)
__device__ unsigned g_bar_count = 0;
__device__ unsigned g_bar_gen   = 0;

__device__ __forceinline__ void red_add_v4(float* p, float a, float b, float c, float d) {
    asm volatile("red.global.add.v4.f32 [%0], {%1,%2,%3,%4};"
                 :: "l"(p), "f"(a), "f"(b), "f"(c), "f"(d) : "memory");
}

__device__ __forceinline__ void grid_sync() {
    __threadfence();                     // release all this thread's writes
    __syncthreads();
    if (threadIdx.x == 0) {
        unsigned gen = *(volatile unsigned*)&g_bar_gen;
        if (atomicAdd(&g_bar_count, 1u) == NBLK - 1) {
            g_bar_count = 0;
            __threadfence();
            *(volatile unsigned*)&g_bar_gen = gen + 1;
        } else {
            while (*(volatile unsigned*)&g_bar_gen == gen) __nanosleep(64);
        }
        __threadfence();                 // acquire
    }
    __syncthreads();
}

__global__ void __launch_bounds__(NTHR, 4)
k_all(const float* __restrict__ x1, const int* __restrict__ e1,
      const float* __restrict__ W1, const float* __restrict__ as1,
      const float* __restrict__ ad1, const float* __restrict__ b1,
      const float* __restrict__ x2, const int* __restrict__ e2,
      const float* __restrict__ W2, const float* __restrict__ as2,
      const float* __restrict__ ad2, const float* __restrict__ b2,
      const float* __restrict__ Wl, const float* __restrict__ bl,
      float* __restrict__ out) {
    __shared__ float sbuf[2304];        // phase1: su[2048]; phase5: sG|smemb|sred
    const int tid  = threadIdx.x;
    const int b    = blockIdx.x;
    const int gtid = b * NTHR + tid;

    // ================= phase 0: zero scratch, dtype detect, u fold =================
    if (gtid < 2 * NA) {
        ((float*)g_den)[gtid]  = 0.0f;
        ((float*)g_wsrc)[gtid] = 0.0f;
    }
    if (gtid < 2 * NH * IN_DIM) ((float*)g_G)[gtid] = 0.0f;
    if (gtid == 0) {
        int all0 = 1;
        #pragma unroll
        for (int i = 0; i < 64; i++)
            if (e1[2 * i + 1] != 0) { all0 = 0; break; }
        g_is64 = all0;
    }
    {   // u[k][h] = sum_c W[k, h*128+c] * att[h,c]  -- one warp per (g,which,k)
        int w = gtid >> 5, lane = gtid & 31;
        if (w < 512) {
            int g = w >> 8, which = (w >> 7) & 1, k = w & 127;
            const float* W   = g ? W2 : W1;
            const float* att = g ? (which ? ad2 : as2) : (which ? ad1 : as1);
            #pragma unroll
            for (int h = 0; h < 8; h++) {
                float4 wv = *reinterpret_cast<const float4*>(W + k * HC + h * 128 + lane * 4);
                float4 av = *reinterpret_cast<const float4*>(att + h * 128 + lane * 4);
                float s = wv.x * av.x + wv.y * av.y + wv.z * av.z + wv.w * av.w;
                #pragma unroll
                for (int off = 16; off; off >>= 1) s += __shfl_xor_sync(0xffffffffu, s, off);
                if (lane == 0) {
                    if (which) g_udst[g][k * NH + h] = s;
                    else       g_usrc[g][k * NH + h] = s;
                }
            }
        }
    }
    grid_sync();

    // ================= phase 1: a = x @ [usrc | udst]  (blocks 0..63) =================
    if (b < 64) {
        int g = b >> 5;
        const float* x = g ? x2 : x1;
        for (int k = tid; k < IN_DIM; k += NTHR) {
            #pragma unroll
            for (int j = 0; j < 8; j++) {
                sbuf[k * 16 + j]     = g_usrc[g][k * 8 + j];
                sbuf[k * 16 + 8 + j] = g_udst[g][k * 8 + j];
            }
        }
        __syncthreads();
        int n = (b & 31) * 256 + tid;
        const float4* xr  = reinterpret_cast<const float4*>(x + n * IN_DIM);
        const float4* su4 = reinterpret_cast<const float4*>(sbuf);
        float acc[16];
        #pragma unroll
        for (int j = 0; j < 16; j++) acc[j] = 0.0f;
        #pragma unroll 4
        for (int k4 = 0; k4 < 32; k4++) {
            float4 xv = xr[k4];
            float xs[4] = {xv.x, xv.y, xv.z, xv.w};
            #pragma unroll
            for (int s = 0; s < 4; s++) {
                int b4 = (k4 * 4 + s) * 4;
                float4 u0 = su4[b4], u1 = su4[b4 + 1], u2 = su4[b4 + 2], u3 = su4[b4 + 3];
                acc[0]  += xs[s] * u0.x;  acc[1]  += xs[s] * u0.y;
                acc[2]  += xs[s] * u0.z;  acc[3]  += xs[s] * u0.w;
                acc[4]  += xs[s] * u1.x;  acc[5]  += xs[s] * u1.y;
                acc[6]  += xs[s] * u1.z;  acc[7]  += xs[s] * u1.w;
                acc[8]  += xs[s] * u2.x;  acc[9]  += xs[s] * u2.y;
                acc[10] += xs[s] * u2.z;  acc[11] += xs[s] * u2.w;
                acc[12] += xs[s] * u3.x;  acc[13] += xs[s] * u3.y;
                acc[14] += xs[s] * u3.z;  acc[15] += xs[s] * u3.w;
            }
        }
        float4* oa = reinterpret_cast<float4*>(g_asrc[g] + n * NH);
        float4* od = reinterpret_cast<float4*>(g_adst[g] + n * NH);
        oa[0] = make_float4(acc[0], acc[1], acc[2], acc[3]);
        oa[1] = make_float4(acc[4], acc[5], acc[6], acc[7]);
        od[0] = make_float4(acc[8], acc[9], acc[10], acc[11]);
        od[1] = make_float4(acc[12], acc[13], acc[14], acc[15]);
    }
    grid_sync();

    // ================= phase 2: edge pass 1 (keep state in registers) =================
    int   esrc[EPT], edst[EPT], eg[EPT];
    uint4 exh[EPT];
    {
        const int is64 = g_is64;
        #pragma unroll
        for (int i = 0; i < EPT; i++) {
            int t = gtid + i * TOTNT;
            if (t < 2 * TOTAL_E) {
                int g = (t >= TOTAL_E);
                int idx = t - g * TOTAL_E;
                const int* e32 = g ? e2 : e1;
                int src, dst;
                if (idx < N_EDGES) {
                    if (is64) { src = e32[2 * idx]; dst = e32[2 * (N_EDGES + idx)]; }
                    else      { src = e32[idx];     dst = e32[N_EDGES + idx]; }
                } else { src = dst = idx - N_EDGES; }
                esrc[i] = src; edst[i] = dst; eg[i] = g;

                const float4* as4 = reinterpret_cast<const float4*>(g_asrc[g] + src * NH);
                const float4* ad4 = reinterpret_cast<const float4*>(g_adst[g] + dst * NH);
                float4 s0 = as4[0], s1 = as4[1], d0 = ad4[0], d1 = ad4[1];
                float ev[8] = { s0.x + d0.x, s0.y + d0.y, s0.z + d0.z, s0.w + d0.w,
                                s1.x + d1.x, s1.y + d1.y, s1.z + d1.z, s1.w + d1.w };
                float ex[8];
                #pragma unroll
                for (int h = 0; h < 8; h++) {
                    float v = ev[h];
                    v = (v > 0.0f) ? v : 0.2f * v;
                    ex[h] = __expf(v);
                }
                __half2 hx[4];
                #pragma unroll
                for (int p = 0; p < 4; p++) hx[p] = __floats2half2_rn(ex[2*p], ex[2*p+1]);
                exh[i] = *reinterpret_cast<uint4*>(hx);

                float* den = g_den[g] + dst * NH;
                red_add_v4(den,     ex[0], ex[1], ex[2], ex[3]);
                red_add_v4(den + 4, ex[4], ex[5], ex[6], ex[7]);
            } else {
                esrc[i] = -1;
            }
        }
    }
    grid_sync();

    // ================= phase 3: edge pass 2: Wsrc[src] += ex / den[dst] =================
    {
        #pragma unroll
        for (int i = 0; i < EPT; i++) {
            if (esrc[i] >= 0) {
                int g = eg[i];
                const __half2* hx = reinterpret_cast<const __half2*>(&exh[i]);
                float ex[8];
                #pragma unroll
                for (int p = 0; p < 4; p++) {
                    float2 f = __half22float2(hx[p]);
                    ex[2*p] = f.x; ex[2*p+1] = f.y;
                }
                const float4* dn4 = reinterpret_cast<const float4*>(g_den[g] + edst[i] * NH);
                float4 n0 = dn4[0], n1 = dn4[1];
                float dn[8] = { n0.x, n0.y, n0.z, n0.w, n1.x, n1.y, n1.z, n1.w };
                float a[8];
                #pragma unroll
                for (int h = 0; h < 8; h++) a[h] = __fdividef(ex[h], dn[h]);
                float* ws = g_wsrc[g] + esrc[i] * NH;
                red_add_v4(ws,     a[0], a[1], a[2], a[3]);
                red_add_v4(ws + 4, a[4], a[5], a[6], a[7]);
            }
        }
    }
    grid_sync();

    // ================= phase 4: G[h,k] = sum_n Wsrc[n,h] * x[n,k] (blocks 0..127) ======
    if (b < 128) {
        int g  = b >> 6;
        int n0 = (b & 63) * 128;
        int k  = tid & 127, half = tid >> 7;
        const float* x = g ? x2 : x1;
        float acc[NH];
        #pragma unroll
        for (int h = 0; h < NH; h++) acc[h] = 0.0f;
        for (int i = half * 64; i < half * 64 + 64; i++) {
            int n = n0 + i;
            float xv = x[n * IN_DIM + k];
            const float4* w4 = reinterpret_cast<const float4*>(g_wsrc[g] + n * NH);
            float4 wa = w4[0], wb = w4[1];
            acc[0] += wa.x * xv; acc[1] += wa.y * xv; acc[2] += wa.z * xv; acc[3] += wa.w * xv;
            acc[4] += wb.x * xv; acc[5] += wb.y * xv; acc[6] += wb.z * xv; acc[7] += wb.w * xv;
        }
        #pragma unroll
        for (int h = 0; h < NH; h++) atomicAdd(&g_G[g][h * IN_DIM + k], acc[h]);
    }
    grid_sync();

    // ================= phase 5: fused memb + out (blocks 0,1) =================
    if (b < 2) {
        float* sG    = sbuf;          // 1024
        float* smemb = sbuf + 1024;   // 1024
        float* sred  = sbuf + 2048;   // 256
        int g = 1 - b;                // out slice b uses the other graph's mean emb
        const float* W  = g ? W2 : W1;
        const float* bb = g ? b2 : b1;

        #pragma unroll
        for (int i = 0; i < 4; i++) sG[tid + i * 256] = g_G[g][tid + i * 256];
        __syncthreads();

        {   // memb[j0..j0+3]
            int j0 = tid * 4;
            int hh = j0 >> 7;
            const float* Gr = sG + hh * IN_DIM;
            float4 s = make_float4(0.f, 0.f, 0.f, 0.f);
            #pragma unroll 4
            for (int k = 0; k < IN_DIM; k++) {
                float gv = Gr[k];
                float4 w4 = *reinterpret_cast<const float4*>(W + k * HC + j0);
                s.x += gv * w4.x; s.y += gv * w4.y; s.z += gv * w4.z; s.w += gv * w4.w;
            }
            const float inv = 1.0f / N_NODES;
            smemb[j0]     = s.x * inv + bb[j0];
            smemb[j0 + 1] = s.y * inv + bb[j0 + 1];
            smemb[j0 + 2] = s.z * inv + bb[j0 + 2];
            smemb[j0 + 3] = s.w * inv + bb[j0 + 3];
        }
        __syncthreads();

        {   // out[b*128+c] = sum_j smemb[j] * Wl[j*128+c] + bl[c]
            int c = tid & 127, half = tid >> 7;
            float s = 0.0f;
            #pragma unroll 4
            for (int j = half * 512; j < half * 512 + 512; j++)
                s += smemb[j] * Wl[j * 128 + c];
            sred[tid] = s;
            __syncthreads();
            if (tid < 128)
                out[b * 128 + c] = sred[c] + sred[128 + c] + bl[c];
        }
    }
}

extern "C" void kernel_launch(void* const* d_in, const int* in_sizes, int n_in,
                              void* d_out, int out_size) {
    k_all<<<NBLK, NTHR>>>(
        (const float*)d_in[0],  (const int*)d_in[1],   (const float*)d_in[2],
        (const float*)d_in[3],  (const float*)d_in[4], (const float*)d_in[5],
        (const float*)d_in[6],  (const int*)d_in[7],   (const float*)d_in[8],
        (const float*)d_in[9],  (const float*)d_in[10],(const float*)d_in[11],
        (const float*)d_in[12], (const float*)d_in[13],
        (float*)d_out);
}

// round 6
// speedup vs baseline: 3.8282x; 1.2330x over previous
#include <cuda_runtime.h>
#include <cuda_fp16.h>

#define N_NODES 8192
#define N_EDGES 262144
#define NH 8
#define IN_DIM 128
#define HC 1024
#define TOTAL_E (N_EDGES + N_NODES)
#define NA (N_NODES * NH)

#define NBLK 592
#define NTHR 256
#define TOTNT (NBLK * NTHR)
#define EPT 4

// ---------------- device scratch ----------------
__device__ __align__(128) float g_asrc[2][NA];
__device__ __align__(128) float g_adst[2][NA];
__device__ __align__(128) float g_den [2][NA];
__device__ __align__(128) float g_wsrc[2][NA];
__device__ __align__(128) float g_usrc[2][IN_DIM * NH];
__device__ __align__(128) float g_udst[2][IN_DIM * NH];
__device__ __align__(128) float g_G   [2][NH * IN_DIM];
__device__ __align__(128) float g_memb[2][HC];
__device__ int g_is64;

__device__ unsigned g_bar_count = 0;
__device__ unsigned g_bar_gen   = 0;

__device__ __forceinline__ void red_add_v4(float* p, float a, float b, float c, float d) {
    asm volatile("red.global.add.v4.f32 [%0], {%1,%2,%3,%4};"
                 :: "l"(p), "f"(a), "f"(b), "f"(c), "f"(d) : "memory");
}
__device__ __forceinline__ void red_add_f(float* p, float a) {
    asm volatile("red.global.add.f32 [%0], %1;" :: "l"(p), "f"(a) : "memory");
}

__device__ __forceinline__ void grid_sync() {
    __threadfence();
    __syncthreads();
    if (threadIdx.x == 0) {
        unsigned gen = *(volatile unsigned*)&g_bar_gen;
        if (atomicAdd(&g_bar_count, 1u) == NBLK - 1) {
            g_bar_count = 0;
            __threadfence();
            *(volatile unsigned*)&g_bar_gen = gen + 1;
        } else {
            while (*(volatile unsigned*)&g_bar_gen == gen) __nanosleep(32);
        }
        __threadfence();
    }
    __syncthreads();
}

__global__ void __launch_bounds__(NTHR, 4)
k_all(const float* __restrict__ x1, const int* __restrict__ e1,
      const float* __restrict__ W1, const float* __restrict__ as1,
      const float* __restrict__ ad1, const float* __restrict__ b1,
      const float* __restrict__ x2, const int* __restrict__ e2,
      const float* __restrict__ W2, const float* __restrict__ as2,
      const float* __restrict__ ad2, const float* __restrict__ b2,
      const float* __restrict__ Wl, const float* __restrict__ bl,
      float* __restrict__ out) {
    __shared__ float sbuf[2304];
    const int tid  = threadIdx.x;
    const int b    = blockIdx.x;
    const int gtid = b * NTHR + tid;

    // ========== P0: zero scratch, zero out, dtype detect, u fold ==========
    if (gtid < 2 * NA) {
        ((float*)g_den)[gtid]  = 0.0f;
        ((float*)g_wsrc)[gtid] = 0.0f;
    }
    if (gtid < 2 * NH * IN_DIM) ((float*)g_G)[gtid] = 0.0f;
    if (gtid < 256) out[gtid] = 0.0f;
    if (gtid == 0) {
        int all0 = 1;
        #pragma unroll
        for (int i = 0; i < 64; i++)
            if (e1[2 * i + 1] != 0) { all0 = 0; break; }
        g_is64 = all0;
    }
    {   // u[k][h] = sum_c W[k, h*128+c] * att[h,c]  — warp per (g,which,k)
        int w = gtid >> 5, lane = gtid & 31;
        if (w < 512) {
            int g = w >> 8, which = (w >> 7) & 1, k = w & 127;
            const float* W   = g ? W2 : W1;
            const float* att = g ? (which ? ad2 : as2) : (which ? ad1 : as1);
            #pragma unroll
            for (int h = 0; h < 8; h++) {
                float4 wv = *reinterpret_cast<const float4*>(W + k * HC + h * 128 + lane * 4);
                float4 av = *reinterpret_cast<const float4*>(att + h * 128 + lane * 4);
                float s = wv.x * av.x + wv.y * av.y + wv.z * av.z + wv.w * av.w;
                #pragma unroll
                for (int off = 16; off; off >>= 1) s += __shfl_xor_sync(0xffffffffu, s, off);
                if (lane == 0) {
                    if (which) g_udst[g][k * NH + h] = s;
                    else       g_usrc[g][k * NH + h] = s;
                }
            }
        }
    }
    grid_sync();

    // ========== P1: a = x @ [usrc|udst], 2 threads per node, blocks 0..127 ==========
    if (b < 128) {
        int g = b >> 6;
        const float* x = g ? x2 : x1;
        for (int k = tid; k < IN_DIM; k += NTHR) {
            #pragma unroll
            for (int j = 0; j < 8; j++) {
                sbuf[k * 16 + j]     = g_usrc[g][k * 8 + j];
                sbuf[k * 16 + 8 + j] = g_udst[g][k * 8 + j];
            }
        }
        __syncthreads();
        int n    = (b & 63) * 128 + (tid >> 1);
        int kpar = tid & 1;
        const float* xr = x + n * IN_DIM;
        float acc[16];
        #pragma unroll
        for (int j = 0; j < 16; j++) acc[j] = 0.0f;
        #pragma unroll 8
        for (int j = 0; j < 64; j++) {
            int k = 2 * j + kpar;
            float xv = xr[k];
            const float* uk = sbuf + k * 16;
            #pragma unroll
            for (int q = 0; q < 16; q++) acc[q] += xv * uk[q];
        }
        #pragma unroll
        for (int q = 0; q < 16; q++) acc[q] += __shfl_xor_sync(0xffffffffu, acc[q], 1);
        if (kpar == 0) {
            float4* oa = reinterpret_cast<float4*>(g_asrc[g] + n * NH);
            oa[0] = make_float4(acc[0], acc[1], acc[2], acc[3]);
            oa[1] = make_float4(acc[4], acc[5], acc[6], acc[7]);
        } else {
            float4* od = reinterpret_cast<float4*>(g_adst[g] + n * NH);
            od[0] = make_float4(acc[8],  acc[9],  acc[10], acc[11]);
            od[1] = make_float4(acc[12], acc[13], acc[14], acc[15]);
        }
    }
    grid_sync();

    // ========== P2: edge pass 1 (state in registers) ==========
    int   esrc[EPT], edst[EPT], eg[EPT];
    uint4 exh[EPT];
    {
        const int is64 = g_is64;
        #pragma unroll
        for (int i = 0; i < EPT; i++) {
            int t = gtid + i * TOTNT;
            if (t < 2 * TOTAL_E) {
                int g = (t >= TOTAL_E);
                int idx = t - g * TOTAL_E;
                const int* e32 = g ? e2 : e1;
                int src, dst;
                if (idx < N_EDGES) {
                    if (is64) { src = e32[2 * idx]; dst = e32[2 * (N_EDGES + idx)]; }
                    else      { src = e32[idx];     dst = e32[N_EDGES + idx]; }
                } else { src = dst = idx - N_EDGES; }
                esrc[i] = src; edst[i] = dst; eg[i] = g;

                const float4* as4 = reinterpret_cast<const float4*>(g_asrc[g] + src * NH);
                const float4* ad4 = reinterpret_cast<const float4*>(g_adst[g] + dst * NH);
                float4 s0 = as4[0], s1 = as4[1], d0 = ad4[0], d1 = ad4[1];
                float ev[8] = { s0.x + d0.x, s0.y + d0.y, s0.z + d0.z, s0.w + d0.w,
                                s1.x + d1.x, s1.y + d1.y, s1.z + d1.z, s1.w + d1.w };
                float ex[8];
                #pragma unroll
                for (int h = 0; h < 8; h++) {
                    float v = ev[h];
                    v = (v > 0.0f) ? v : 0.2f * v;
                    ex[h] = __expf(v);
                }
                __half2 hx[4];
                #pragma unroll
                for (int p = 0; p < 4; p++) hx[p] = __floats2half2_rn(ex[2*p], ex[2*p+1]);
                exh[i] = *reinterpret_cast<uint4*>(hx);

                float* den = g_den[g] + dst * NH;
                red_add_v4(den,     ex[0], ex[1], ex[2], ex[3]);
                red_add_v4(den + 4, ex[4], ex[5], ex[6], ex[7]);
            } else {
                esrc[i] = -1;
            }
        }
    }
    grid_sync();

    // ========== P3: edge pass 2: Wsrc[src] += ex / den[dst] ==========
    {
        #pragma unroll
        for (int i = 0; i < EPT; i++) {
            if (esrc[i] >= 0) {
                int g = eg[i];
                const __half2* hx = reinterpret_cast<const __half2*>(&exh[i]);
                float ex[8];
                #pragma unroll
                for (int p = 0; p < 4; p++) {
                    float2 f = __half22float2(hx[p]);
                    ex[2*p] = f.x; ex[2*p+1] = f.y;
                }
                const float4* dn4 = reinterpret_cast<const float4*>(g_den[g] + edst[i] * NH);
                float4 n0 = dn4[0], n1 = dn4[1];
                float dn[8] = { n0.x, n0.y, n0.z, n0.w, n1.x, n1.y, n1.z, n1.w };
                float a[8];
                #pragma unroll
                for (int h = 0; h < 8; h++) a[h] = __fdividef(ex[h], dn[h]);
                float* ws = g_wsrc[g] + esrc[i] * NH;
                red_add_v4(ws,     a[0], a[1], a[2], a[3]);
                red_add_v4(ws + 4, a[4], a[5], a[6], a[7]);
            }
        }
    }
    grid_sync();

    // ========== P4: G[h,k] += sum_n Wsrc[n,h]*x[n,k], blocks 0..511 ==========
    if (b < 512) {
        int g  = b >> 8;
        int n0 = (b & 255) * 32;
        int k  = tid & 127, half = tid >> 7;
        const float* x = g ? x2 : x1;
        float acc[NH];
        #pragma unroll
        for (int h = 0; h < NH; h++) acc[h] = 0.0f;
        for (int i = half * 16; i < half * 16 + 16; i++) {
            int n = n0 + i;
            float xv = x[n * IN_DIM + k];
            const float4* w4 = reinterpret_cast<const float4*>(g_wsrc[g] + n * NH);
            float4 wa = w4[0], wb = w4[1];
            acc[0] += wa.x * xv; acc[1] += wa.y * xv; acc[2] += wa.z * xv; acc[3] += wa.w * xv;
            acc[4] += wb.x * xv; acc[5] += wb.y * xv; acc[6] += wb.z * xv; acc[7] += wb.w * xv;
        }
        #pragma unroll
        for (int h = 0; h < NH; h++) atomicAdd(&g_G[g][h * IN_DIM + k], acc[h]);
    }
    grid_sync();

    // ========== P5a: memb[g][jc*128 .. +128), blocks 0..15 ==========
    if (b < 16) {
        int g  = b >> 3;           // graph
        int jc = b & 7;            // j chunk == head
        const float* W  = g ? W2 : W1;
        const float* bb = g ? b2 : b1;
        float* sG   = sbuf;        // 128: G row for head jc
        float* sred = sbuf + 128;  // 256
        if (tid < 128) sG[tid] = g_G[g][jc * 128 + tid];
        __syncthreads();
        int j = jc * 128 + (tid & 127);
        int kh = tid >> 7;
        float s = 0.0f;
        #pragma unroll 4
        for (int k = kh * 64; k < kh * 64 + 64; k++)
            s += sG[k] * W[k * HC + j];
        sred[tid] = s;
        __syncthreads();
        if (tid < 128)
            g_memb[g][j] = (sred[tid] + sred[tid + 128]) * (1.0f / N_NODES) + bb[j];
    }
    grid_sync();

    // ========== P5b: out[s*128+c] += sum_{j in chunk} memb[1-s][j]*Wl[j,c], blocks 0..15 ==========
    if (b < 16) {
        int s  = b >> 3;           // out slice
        int jc = b & 7;            // j chunk
        int g  = 1 - s;            // slice s uses the other graph's mean emb
        float* sm   = sbuf;        // 128
        float* sred = sbuf + 128;  // 256
        if (tid < 128) sm[tid] = g_memb[g][jc * 128 + tid];
        __syncthreads();
        int c  = tid & 127;
        int jh = tid >> 7;
        float acc = 0.0f;
        #pragma unroll 4
        for (int jl = jh * 64; jl < jh * 64 + 64; jl++)
            acc += sm[jl] * Wl[(jc * 128 + jl) * 128 + c];
        sred[tid] = acc;
        __syncthreads();
        if (tid < 128) {
            float v = sred[tid] + sred[tid + 128];
            if (jc == 0) v += bl[c];
            red_add_f(&out[s * 128 + c], v);
        }
    }
}

extern "C" void kernel_launch(void* const* d_in, const int* in_sizes, int n_in,
                              void* d_out, int out_size) {
    k_all<<<NBLK, NTHR>>>(
        (const float*)d_in[0],  (const int*)d_in[1],   (const float*)d_in[2],
        (const float*)d_in[3],  (const float*)d_in[4], (const float*)d_in[5],
        (const float*)d_in[6],  (const int*)d_in[7],   (const float*)d_in[8],
        (const float*)d_in[9],  (const float*)d_in[10],(const float*)d_in[11],
        (const float*)d_in[12], (const float*)d_in[13],
        (float*)d_out);
}

// round 8
// speedup vs baseline: 3.9164x; 1.0230x over previous
#include <cuda_runtime.h>
#include <cuda_fp16.h>

#define N_NODES 8192
#define N_EDGES 262144
#define NH 8
#define IN_DIM 128
#define HC 1024
#define TOTAL_E (N_EDGES + N_NODES)     // 270336, divisible by 4
#define NA (N_NODES * NH)

#define NBLK 592
#define NTHR 256
#define TOTNT (NBLK * NTHR)
#define EPT 4
#define QUADS_PER_G (TOTAL_E / 4)       // 67584
#define EDGE_THREADS (2 * QUADS_PER_G)  // 135168

// ---------------- device scratch ----------------
__device__ __align__(128) float g_asrc[2][NA];
__device__ __align__(128) float g_adst[2][NA];
__device__ __align__(128) float g_den [2][NA];
__device__ __align__(128) float g_wsrc[2][NA];
__device__ __align__(128) float g_usrc[2][IN_DIM * NH];
__device__ __align__(128) float g_udst[2][IN_DIM * NH];
__device__ __align__(128) float g_G   [2][NH * IN_DIM];
__device__ __align__(128) float g_memb[2][HC];
__device__ int g_is64;

__device__ unsigned g_bar_count = 0;
__device__ unsigned g_bar_gen   = 0;

__device__ __forceinline__ void red_add_v4(float* p, float a, float b, float c, float d) {
    asm volatile("red.global.add.v4.f32 [%0], {%1,%2,%3,%4};"
                 :: "l"(p), "f"(a), "f"(b), "f"(c), "f"(d) : "memory");
}
__device__ __forceinline__ void red_add_f(float* p, float a) {
    asm volatile("red.global.add.f32 [%0], %1;" :: "l"(p), "f"(a) : "memory");
}

__device__ __forceinline__ void grid_sync() {
    __threadfence();
    __syncthreads();
    if (threadIdx.x == 0) {
        unsigned gen = *(volatile unsigned*)&g_bar_gen;
        if (atomicAdd(&g_bar_count, 1u) == NBLK - 1) {
            g_bar_count = 0;
            __threadfence();
            *(volatile unsigned*)&g_bar_gen = gen + 1;
        } else {
            while (*(volatile unsigned*)&g_bar_gen == gen) __nanosleep(32);
        }
        __threadfence();
    }
    __syncthreads();
}

__global__ void __launch_bounds__(NTHR, 4)
k_all(const float* __restrict__ x1, const int* __restrict__ e1,
      const float* __restrict__ W1, const float* __restrict__ as1,
      const float* __restrict__ ad1, const float* __restrict__ b1,
      const float* __restrict__ x2, const int* __restrict__ e2,
      const float* __restrict__ W2, const float* __restrict__ as2,
      const float* __restrict__ ad2, const float* __restrict__ b2,
      const float* __restrict__ Wl, const float* __restrict__ bl,
      float* __restrict__ out) {
    __shared__ float sbuf[2304];
    const int tid  = threadIdx.x;
    const int b    = blockIdx.x;
    const int gtid = b * NTHR + tid;

    // edge ownership: 4 CONSECUTIVE edges of one graph per thread
    const int  eg    = (gtid >= QUADS_PER_G);
    const bool has_e = (gtid < EDGE_THREADS);
    const int  ebase = has_e ? (gtid - eg * QUADS_PER_G) * 4 : 0;
    const int* eptr  = eg ? e2 : e1;

    // ========== P0: zero scratch, zero out, dtype detect, u fold ==========
    if (gtid < 2 * NA) {
        ((float*)g_den)[gtid]  = 0.0f;
        ((float*)g_wsrc)[gtid] = 0.0f;
    }
    if (gtid < 2 * NH * IN_DIM) ((float*)g_G)[gtid] = 0.0f;
    if (gtid < 256) out[gtid] = 0.0f;
    if (gtid == 0) {
        int all0 = 1;
        #pragma unroll
        for (int i = 0; i < 64; i++)
            if (e1[2 * i + 1] != 0) { all0 = 0; break; }
        g_is64 = all0;
    }
    {   // u[k][h] = sum_c W[k, h*128+c] * att[h,c]  — warp per (g,which,k)
        int w = gtid >> 5, lane = gtid & 31;
        if (w < 512) {
            int g = w >> 8, which = (w >> 7) & 1, k = w & 127;
            const float* W   = g ? W2 : W1;
            const float* att = g ? (which ? ad2 : as2) : (which ? ad1 : as1);
            #pragma unroll
            for (int h = 0; h < 8; h++) {
                float4 wv = *reinterpret_cast<const float4*>(W + k * HC + h * 128 + lane * 4);
                float4 av = *reinterpret_cast<const float4*>(att + h * 128 + lane * 4);
                float s = wv.x * av.x + wv.y * av.y + wv.z * av.z + wv.w * av.w;
                #pragma unroll
                for (int off = 16; off; off >>= 1) s += __shfl_xor_sync(0xffffffffu, s, off);
                if (lane == 0) {
                    if (which) g_udst[g][k * NH + h] = s;
                    else       g_usrc[g][k * NH + h] = s;
                }
            }
        }
    }
    grid_sync();

    // ========== P1: a = x @ [usrc|udst], 2 threads per node, blocks 0..127 ==========
    if (b < 128) {
        int g = b >> 6;
        const float* x = g ? x2 : x1;
        for (int k = tid; k < IN_DIM; k += NTHR) {
            #pragma unroll
            for (int j = 0; j < 8; j++) {
                sbuf[k * 16 + j]     = g_usrc[g][k * 8 + j];
                sbuf[k * 16 + 8 + j] = g_udst[g][k * 8 + j];
            }
        }
        __syncthreads();
        int n    = (b & 63) * 128 + (tid >> 1);
        int kpar = tid & 1;
        const float* xr = x + n * IN_DIM;
        float acc[16];
        #pragma unroll
        for (int j = 0; j < 16; j++) acc[j] = 0.0f;
        #pragma unroll 8
        for (int j = 0; j < 64; j++) {
            int k = 2 * j + kpar;
            float xv = xr[k];
            const float* uk = sbuf + k * 16;
            #pragma unroll
            for (int q = 0; q < 16; q++) acc[q] += xv * uk[q];
        }
        #pragma unroll
        for (int q = 0; q < 16; q++) acc[q] += __shfl_xor_sync(0xffffffffu, acc[q], 1);
        if (kpar == 0) {
            float4* oa = reinterpret_cast<float4*>(g_asrc[g] + n * NH);
            oa[0] = make_float4(acc[0], acc[1], acc[2], acc[3]);
            oa[1] = make_float4(acc[4], acc[5], acc[6], acc[7]);
        } else {
            float4* od = reinterpret_cast<float4*>(g_adst[g] + n * NH);
            od[0] = make_float4(acc[8],  acc[9],  acc[10], acc[11]);
            od[1] = make_float4(acc[12], acc[13], acc[14], acc[15]);
        }
    }
    grid_sync();

    // ========== P2: edge pass 1 (coalesced consecutive-edge index loads) ==========
    int   esrc[EPT], edst[EPT];
    uint4 exh[EPT];
    if (has_e) {
        if (ebase < N_EDGES) {
            if (g_is64) {
                // int64 little-endian, values < 2^31: low word at even offsets.
                // int2 loads are 8B-aligned by construction (safe for any base
                // alignment of an int64 array); 4 consecutive edges per thread
                // give fully-utilized 32B sectors.
                #pragma unroll
                for (int i = 0; i < EPT; i++) {
                    int2 sw = *reinterpret_cast<const int2*>(eptr + 2 * (ebase + i));
                    int2 dw = *reinterpret_cast<const int2*>(eptr + 2 * (N_EDGES + ebase + i));
                    esrc[i] = sw.x;
                    edst[i] = dw.x;
                }
            } else {
                #pragma unroll
                for (int i = 0; i < EPT; i++) {
                    esrc[i] = eptr[ebase + i];
                    edst[i] = eptr[N_EDGES + ebase + i];
                }
            }
        } else {
            #pragma unroll
            for (int i = 0; i < EPT; i++) esrc[i] = edst[i] = ebase - N_EDGES + i;
        }
        #pragma unroll
        for (int i = 0; i < EPT; i++) {
            const float4* as4 = reinterpret_cast<const float4*>(g_asrc[eg] + esrc[i] * NH);
            const float4* ad4 = reinterpret_cast<const float4*>(g_adst[eg] + edst[i] * NH);
            float4 s0 = as4[0], s1 = as4[1], d0 = ad4[0], d1 = ad4[1];
            float ev[8] = { s0.x + d0.x, s0.y + d0.y, s0.z + d0.z, s0.w + d0.w,
                            s1.x + d1.x, s1.y + d1.y, s1.z + d1.z, s1.w + d1.w };
            float ex[8];
            #pragma unroll
            for (int h = 0; h < 8; h++) {
                float v = ev[h];
                v = (v > 0.0f) ? v : 0.2f * v;
                ex[h] = __expf(v);
            }
            __half2 hx[4];
            #pragma unroll
            for (int p = 0; p < 4; p++) hx[p] = __floats2half2_rn(ex[2*p], ex[2*p+1]);
            exh[i] = *reinterpret_cast<uint4*>(hx);

            float* den = g_den[eg] + edst[i] * NH;
            red_add_v4(den,     ex[0], ex[1], ex[2], ex[3]);
            red_add_v4(den + 4, ex[4], ex[5], ex[6], ex[7]);
        }
    }
    grid_sync();

    // ========== P3: edge pass 2: Wsrc[src] += ex / den[dst] ==========
    if (has_e) {
        #pragma unroll
        for (int i = 0; i < EPT; i++) {
            const __half2* hx = reinterpret_cast<const __half2*>(&exh[i]);
            float ex[8];
            #pragma unroll
            for (int p = 0; p < 4; p++) {
                float2 f = __half22float2(hx[p]);
                ex[2*p] = f.x; ex[2*p+1] = f.y;
            }
            const float4* dn4 = reinterpret_cast<const float4*>(g_den[eg] + edst[i] * NH);
            float4 n0 = dn4[0], n1 = dn4[1];
            float dn[8] = { n0.x, n0.y, n0.z, n0.w, n1.x, n1.y, n1.z, n1.w };
            float a[8];
            #pragma unroll
            for (int h = 0; h < 8; h++) a[h] = __fdividef(ex[h], dn[h]);
            float* ws = g_wsrc[eg] + esrc[i] * NH;
            red_add_v4(ws,     a[0], a[1], a[2], a[3]);
            red_add_v4(ws + 4, a[4], a[5], a[6], a[7]);
        }
    }
    grid_sync();

    // ========== P4: G[h,k] += sum_n Wsrc[n,h]*x[n,k], blocks 0..511 ==========
    if (b < 512) {
        int g  = b >> 8;
        int n0 = (b & 255) * 32;
        int k  = tid & 127, half = tid >> 7;
        const float* x = g ? x2 : x1;
        float acc[NH];
        #pragma unroll
        for (int h = 0; h < NH; h++) acc[h] = 0.0f;
        for (int i = half * 16; i < half * 16 + 16; i++) {
            int n = n0 + i;
            float xv = x[n * IN_DIM + k];
            const float4* w4 = reinterpret_cast<const float4*>(g_wsrc[g] + n * NH);
            float4 wa = w4[0], wb = w4[1];
            acc[0] += wa.x * xv; acc[1] += wa.y * xv; acc[2] += wa.z * xv; acc[3] += wa.w * xv;
            acc[4] += wb.x * xv; acc[5] += wb.y * xv; acc[6] += wb.z * xv; acc[7] += wb.w * xv;
        }
        #pragma unroll
        for (int h = 0; h < NH; h++) atomicAdd(&g_G[g][h * IN_DIM + k], acc[h]);
    }
    grid_sync();

    // ========== P5a: memb[g][jc*128 .. +128), blocks 0..15 ==========
    if (b < 16) {
        int g  = b >> 3;
        int jc = b & 7;
        const float* W  = g ? W2 : W1;
        const float* bb = g ? b2 : b1;
        float* sG   = sbuf;
        float* sred = sbuf + 128;
        if (tid < 128) sG[tid] = g_G[g][jc * 128 + tid];
        __syncthreads();
        int j = jc * 128 + (tid & 127);
        int kh = tid >> 7;
        float s = 0.0f;
        #pragma unroll 4
        for (int k = kh * 64; k < kh * 64 + 64; k++)
            s += sG[k] * W[k * HC + j];
        sred[tid] = s;
        __syncthreads();
        if (tid < 128)
            g_memb[g][j] = (sred[tid] + sred[tid + 128]) * (1.0f / N_NODES) + bb[j];
    }
    grid_sync();

    // ========== P5b: out[s*128+c] += sum_{j chunk} memb[1-s][j]*Wl[j,c], blocks 0..15 ==
    if (b < 16) {
        int s  = b >> 3;
        int jc = b & 7;
        int g  = 1 - s;
        float* sm   = sbuf;
        float* sred = sbuf + 128;
        if (tid < 128) sm[tid] = g_memb[g][jc * 128 + tid];
        __syncthreads();
        int c  = tid & 127;
        int jh = tid >> 7;
        float acc = 0.0f;
        #pragma unroll 4
        for (int jl = jh * 64; jl < jh * 64 + 64; jl++)
            acc += sm[jl] * Wl[(jc * 128 + jl) * 128 + c];
        sred[tid] = acc;
        __syncthreads();
        if (tid < 128) {
            float v = sred[tid] + sred[tid + 128];
            if (jc == 0) v += bl[c];
            red_add_f(&out[s * 128 + c], v);
        }
    }
}

extern "C" void kernel_launch(void* const* d_in, const int* in_sizes, int n_in,
                              void* d_out, int out_size) {
    k_all<<<NBLK, NTHR>>>(
        (const float*)d_in[0],  (const int*)d_in[1],   (const float*)d_in[2],
        (const float*)d_in[3],  (const float*)d_in[4], (const float*)d_in[5],
        (const float*)d_in[6],  (const int*)d_in[7],   (const float*)d_in[8],
        (const float*)d_in[9],  (const float*)d_in[10],(const float*)d_in[11],
        (const float*)d_in[12], (const float*)d_in[13],
        (float*)d_out);
}